// round 10
// baseline (speedup 1.0000x reference)
#include <cuda_runtime.h>
#include <cuda_fp16.h>
#include <cstdint>

#define HW     56
#define CIN    128
#define COUT   128
#define NB     5
#define WELEMS (COUT * CIN * 9)

// ---------------- device scratch (no allocs allowed) ----------------
__device__ float g_part[40];
// effective weights, fp16, pre-swizzled ldmatrix-ready tiles:
// [tap][chunk][k=64][n=128] ; byte off within tile = k*256 + ((n*2)^((k&7)*16))
__device__ __align__(256) __half g_wB[9 * 2 * 64 * 128];

// ---------------- helpers ----------------
static __device__ __forceinline__ uint32_t smem_u32(const void* p) {
    uint32_t a;
    asm("{ .reg .u64 t; cvta.to.shared.u64 t, %1; cvt.u32.u64 %0, t; }" : "=r"(a) : "l"(p));
    return a;
}

static __device__ __forceinline__ void mma16816(float* c, const uint32_t* a,
                                                uint32_t b0, uint32_t b1) {
    asm volatile(
        "mma.sync.aligned.m16n8k16.row.col.f32.f16.f16.f32 "
        "{%0,%1,%2,%3}, {%4,%5,%6,%7}, {%8,%9}, {%0,%1,%2,%3};"
        : "+f"(c[0]), "+f"(c[1]), "+f"(c[2]), "+f"(c[3])
        : "r"(a[0]), "r"(a[1]), "r"(a[2]), "r"(a[3]), "r"(b0), "r"(b1));
}

static __device__ __forceinline__ void ldsm4t(uint32_t* r, uint32_t addr) {
    asm volatile("ldmatrix.sync.aligned.m8n8.x4.trans.shared.b16 {%0,%1,%2,%3}, [%4];"
                 : "=r"(r[0]), "=r"(r[1]), "=r"(r[2]), "=r"(r[3])
                 : "r"(addr));
}

// ================= prep 1: partial sums of |w| (40 blocks) =================
__global__ void mean_abs_part_kernel(const float* __restrict__ w) {
    int n = blockIdx.x >> 3, seg = blockIdx.x & 7;
    const float* wn = w + (size_t)n * WELEMS + seg * (WELEMS / 8);
    float s = 0.f;
    for (int i = threadIdx.x; i < WELEMS / 8; i += 256) s += fabsf(wn[i]);
    __shared__ float red[256];
    red[threadIdx.x] = s;
    __syncthreads();
    for (int off = 128; off > 0; off >>= 1) {
        if (threadIdx.x < off) red[threadIdx.x] += red[threadIdx.x + off];
        __syncthreads();
    }
    if (threadIdx.x == 0) g_part[blockIdx.x] = red[0];
}

// ====== prep 2: effective weight -> swizzled fp16 B tiles (means inlined) ======
__global__ void build_wB_kernel(const float* __restrict__ w,
                                const float* __restrict__ scales) {
    int idx = blockIdx.x * 256 + threadIdx.x;   // ((kidx*128 + i)*128 + o)
    if (idx >= WELEMS) return;
    // per-base mean(|w|) from partials (L2-broadcast loads, cheap)
    float m[NB];
#pragma unroll
    for (int n = 0; n < NB; n++) {
        float s = 0.f;
#pragma unroll
        for (int j = 0; j < 8; j++) s += __ldg(&g_part[n * 8 + j]);
        m[n] = s / (float)WELEMS;
    }
    int o = idx & 127;            // n (cout)
    int i = (idx >> 7) & 127;     // cin
    int kidx = idx >> 14;         // tap
    float v = 0.f;
#pragma unroll
    for (int n = 0; n < NB; n++) {
        float wv = w[(((size_t)n * COUT + o) * CIN + i) * 9 + kidx];
        float sg = (wv > 0.f) ? 1.f : ((wv < 0.f) ? -1.f : 0.f);
        v += scales[n] * m[n] * sg;
    }
    int chunk = i >> 6;
    int kl = i & 63;
    size_t tile = (size_t)(kidx * 2 + chunk) * 8192;   // in halves
    uint32_t boff = (uint32_t)kl * 256 + (((uint32_t)o * 2) ^ (((uint32_t)kl & 7) * 16));
    g_wB[tile + (boff >> 1)] = __float2half_rn(v);
}

// ===== conv kernel (HMMA implicit GEMM, 256 thr, m32n64 warp tile, 2 CTA/SM) =====
// dyn smem (bytes):
//   [0]      B tiles: 2 bufs x 16384 = 32768
//   [32768]  slab: 32 k-pair rows x 232 words + 16 pad = 7440 words = 29760
#define SM_B      0u
#define SM_SLABH  32768u
#define SMEM_TOTAL 62528

static __device__ __forceinline__ void issue_B(uint32_t sdst, const uint8_t* gsrc, int tid) {
    uint32_t s = sdst + (uint32_t)tid * 64u;
    const uint8_t* g = gsrc + tid * 64;
#pragma unroll
    for (int i = 0; i < 4; i++)
        asm volatile("cp.async.cg.shared.global [%0], [%1], 16;" ::
                     "r"(s + i * 16u), "l"(g + i * 16));
    asm volatile("cp.async.commit_group;" ::: "memory");
}

__global__ void __launch_bounds__(256, 2)
conv_kernel(const float* __restrict__ x, float* __restrict__ out) {
    extern __shared__ __align__(16) uint8_t smem[];
    const uint32_t sb = smem_u32(smem);
    uint32_t* slabh = (uint32_t*)(smem + SM_SLABH);

    const int tid = threadIdx.x;
    const int lane = tid & 31, wid = tid >> 5;
    const int g = lane >> 2, tig = lane & 3;
    const int mw = wid & 3;          // m block of 32  (4 blocks -> M=128)
    const int nw = wid >> 2;         // n half of 64   (2 halves -> N=128)
    const int mf = mw * 32;
    const int r0 = blockIdx.x * 2;   // first output row
    const int b = blockIdx.y;

    // zero slab pad (finite garbage only)
    if (tid < 16) slabh[7424 + tid] = 0;

    float acc[2][8][4];
#pragma unroll
    for (int mb = 0; mb < 2; mb++)
#pragma unroll
        for (int j = 0; j < 8; j++)
#pragma unroll
            for (int q = 0; q < 4; q++) acc[mb][j][q] = 0.f;

    // B ldmatrix lane constants
    const int krow_l = (lane & 7) + ((lane & 8) ? 8 : 0);
    const int nsel = ((lane & 16) ? 8 : 0) + nw * 64;

    issue_B(sb + SM_B, (const uint8_t*)g_wB, tid);   // iter 0 tile

#pragma unroll 1
    for (int iter = 0; iter < 18; iter++) {
        const int chunk = (iter >= 9) ? 1 : 0;
        const int kidx = iter - 9 * chunk;
        const int ky = kidx / 3;
        const int kx = kidx - 3 * ky;

        __syncthreads();   // protects B buf reuse + slab overwrite

        // stage x slab for this 64-channel chunk (constant pad = 1.0)
        if (kidx == 0) {
            const float* xp = x + ((size_t)b * CIN + chunk * 64) * (HW * HW);
#pragma unroll 1
            for (int idx = tid; idx < 64 * 232; idx += 256) {
                int ch = idx / 232;
                int pos = idx - ch * 232;
                int r = pos / 58;
                int c = pos - r * 58;
                int gy = r0 - 1 + r, gx = c - 1;
                float v = 1.0f;
                if ((unsigned)gy < HW && (unsigned)gx < HW)
                    v = __ldg(xp + ch * (HW * HW) + gy * HW + gx);
                int wd = (ch >> 1) * 232 + pos;
                ((__half*)slabh)[wd * 2 + (ch & 1)] = __float2half_rn(v);
            }
        }

        // prefetch next B tile (double buffered)
        if (iter + 1 < 18) {
            int nxt = iter + 1;
            int nc = (nxt >= 9) ? 1 : 0;
            int nk = nxt - 9 * nc;
            issue_B(sb + SM_B + (uint32_t)((nxt & 1) * 16384),
                    (const uint8_t*)g_wB + (size_t)(nk * 2 + nc) * 16384, tid);
            asm volatile("cp.async.wait_group 1;" ::: "memory");
        } else {
            asm volatile("cp.async.wait_group 0;" ::: "memory");
        }
        __syncthreads();

        const uint32_t bbase = sb + SM_B + (uint32_t)((iter & 1) * 16384);

#pragma unroll
        for (int s = 0; s < 4; s++) {
            // ---- A fragments (2 x m16) via plain LDS.32 from k-pair-packed slab ----
            uint32_t ah[2][4];
#pragma unroll
            for (int mb = 0; mb < 2; mb++) {
                const int mfb = mf + mb * 16;
                const int pos0 = ((mfb >> 6) + ky) * 58 + (mfb & 63) + kx + g;
                const int w0 = (s * 8 + tig) * 232 + pos0;
                ah[mb][0] = slabh[w0];
                ah[mb][1] = slabh[w0 + 8];
                ah[mb][2] = slabh[w0 + 4 * 232];
                ah[mb][3] = slabh[w0 + 4 * 232 + 8];
            }

            const uint32_t krow = (uint32_t)(s * 16 + krow_l);
#pragma unroll
            for (int np = 0; np < 4; np++) {
                const uint32_t nn = (uint32_t)(nsel + np * 16);
                const uint32_t boff = krow * 256 + ((nn * 2) ^ ((krow & 7) * 16));
                uint32_t bh[4];
                ldsm4t(bh, bbase + boff);
                mma16816(acc[0][np * 2],     ah[0], bh[0], bh[1]);
                mma16816(acc[0][np * 2 + 1], ah[0], bh[2], bh[3]);
                mma16816(acc[1][np * 2],     ah[1], bh[0], bh[1]);
                mma16816(acc[1][np * 2 + 1], ah[1], bh[2], bh[3]);
            }
        }
    }

    // ---- epilogue: register accumulators -> gmem ----
#pragma unroll
    for (int mb = 0; mb < 2; mb++) {
        const int mfb = mf + mb * 16;
        const int y = r0 + (mfb >> 6);
        const int xa = (mfb & 63) + g;     // <= 55, always valid
        const int xb = xa + 8;
#pragma unroll
        for (int ni = 0; ni < 8; ni++) {
            const int n = nw * 64 + ni * 8 + tig * 2;
            float* p = out + ((size_t)b * COUT + n) * (HW * HW) + y * HW;
            p[xa] = acc[mb][ni][0];
            p[HW * HW + xa] = acc[mb][ni][1];
            if (xb < HW) {
                p[xb] = acc[mb][ni][2];
                p[HW * HW + xb] = acc[mb][ni][3];
            }
        }
    }
}

// ================= launcher =================
extern "C" void kernel_launch(void* const* d_in, const int* in_sizes, int n_in,
                              void* d_out, int out_size) {
    const float* x = (const float*)d_in[0];        // [32,128,56,56]
    const float* w = (const float*)d_in[1];        // [5,128,128,3,3]
    const float* scales = (const float*)d_in[2];   // [5]
    float* out = (float*)d_out;                    // [32,128,56,56]

    cudaFuncSetAttribute(conv_kernel, cudaFuncAttributeMaxDynamicSharedMemorySize,
                         SMEM_TOTAL);

    mean_abs_part_kernel<<<40, 256>>>(w);
    build_wB_kernel<<<(WELEMS + 255) / 256, 256>>>(w, scales);
    conv_kernel<<<dim3(28, 32), 256, SMEM_TOTAL>>>(x, out);
}